// round 1
// baseline (speedup 1.0000x reference)
#include <cuda_runtime.h>
#include <math.h>

// Problem geometry (static: x shape (1, 3, 32, 512, 512), patch 32x32)
#define C       3
#define T       32
#define H       512
#define W       512
#define PS      32              // hc = wc = 32
#define NH      (H / PS)        // 16
#define NW      (W / PS)        // 16
#define NPATCH  (T * NH * NW)   // 8192
#define PATCH_ELEMS (C * PS * PS) // 3072

// Scratch: one partial sum (sum of |x - x_r| over the patch) per patch.
__device__ float g_patch_sum[NPATCH];

// ---------------------------------------------------------------------------
// Kernel 1: one CTA per patch. 256 threads, each loads 3 float4 pairs
// (one per channel). Coalesced: 8 consecutive threads cover one contiguous
// 128-byte row segment of the 32-float patch row.
// ---------------------------------------------------------------------------
__global__ __launch_bounds__(256, 8)
void patch_sum_kernel(const float* __restrict__ x,
                      const float* __restrict__ xr) {
    const int patch = blockIdx.x;          // [0, 8192)
    const int t  = patch >> 8;             // / 256
    const int rem = patch & 255;
    const int ih = rem >> 4;
    const int iw = rem & 15;

    const int tid = threadIdx.x;           // [0, 256)
    const int r = tid >> 3;                // row within patch [0,32)
    const int q = tid & 7;                 // float4 index within row [0,8)

    // base element offset of this thread's float4 for channel c:
    //   ((c*T + t)*H + ih*PS + r)*W + iw*PS + q*4
    const int hrow = ih * PS + r;
    const int wcol = iw * PS + q * 4;
    const int base0 = (t * H + hrow) * W + wcol;        // channel 0
    const int cstride = T * H * W;                      // 32*512*512

    float s = 0.0f;
#pragma unroll
    for (int c = 0; c < C; ++c) {
        const int idx = base0 + c * cstride;
        const float4 a = __ldg(reinterpret_cast<const float4*>(x  + idx));
        const float4 b = __ldg(reinterpret_cast<const float4*>(xr + idx));
        s += fabsf(a.x - b.x) + fabsf(a.y - b.y)
           + fabsf(a.z - b.z) + fabsf(a.w - b.w);
    }

    // Block reduction: warp shfl then smem across 8 warps.
#pragma unroll
    for (int off = 16; off > 0; off >>= 1)
        s += __shfl_down_sync(0xFFFFFFFFu, s, off);

    __shared__ float warp_sums[8];
    const int lane = tid & 31;
    const int wid  = tid >> 5;
    if (lane == 0) warp_sums[wid] = s;
    __syncthreads();

    if (wid == 0) {
        float v = (lane < 8) ? warp_sums[lane] : 0.0f;
#pragma unroll
        for (int off = 4; off > 0; off >>= 1)
            v += __shfl_down_sync(0xFFFFFFFFu, v, off);
        if (lane == 0) g_patch_sum[patch] = v;
    }
}

// ---------------------------------------------------------------------------
// Kernel 2: single CTA, 1024 threads. Warp t max-reduces its frame's 256
// patch sums; thread 0 combines: log( mean_t( max_patch * 0.5 / 3072 ) ).
// Clamp at 0 from the reference is vacuous (sums of abs are >= 0).
// ---------------------------------------------------------------------------
__global__ __launch_bounds__(1024, 1)
void patch_final_kernel(float* __restrict__ out) {
    const int tid  = threadIdx.x;
    const int wid  = tid >> 5;   // warp == frame t, [0,32)
    const int lane = tid & 31;

    float m = -1.0f;             // sums are >= 0, so any negative sentinel ok
#pragma unroll
    for (int j = 0; j < 8; ++j) {
        const float v = g_patch_sum[wid * 256 + j * 32 + lane];
        m = fmaxf(m, v);
    }
#pragma unroll
    for (int off = 16; off > 0; off >>= 1)
        m = fmaxf(m, __shfl_down_sync(0xFFFFFFFFu, m, off));

    __shared__ float frame_max[32];
    if (lane == 0) frame_max[wid] = m;
    __syncthreads();

    if (tid == 0) {
        float acc = 0.0f;
#pragma unroll
        for (int t = 0; t < T; ++t)
            acc += fmaxf(frame_max[t], 0.0f);
        // P = sum * 0.5 / 3072 ; mean over T frames ; log
        const float scale = 0.5f / ((float)PATCH_ELEMS * (float)T);
        out[0] = logf(acc * scale);
    }
}

extern "C" void kernel_launch(void* const* d_in, const int* in_sizes, int n_in,
                              void* d_out, int out_size) {
    const float* x  = (const float*)d_in[0];
    const float* xr = (const float*)d_in[1];
    float* out = (float*)d_out;

    patch_sum_kernel<<<NPATCH, 256>>>(x, xr);
    patch_final_kernel<<<1, 1024>>>(out);
}

// round 4
// speedup vs baseline: 1.0072x; 1.0072x over previous
#include <cuda_runtime.h>
#include <math.h>

// Problem geometry (static: x shape (1, 3, 32, 512, 512), patch 32x32)
#define C       3
#define T       32
#define H       512
#define W       512
#define PS      32              // hc = wc = 32
#define NH      (H / PS)        // 16
#define NW      (W / PS)        // 16
#define NPATCH  (T * NH * NW)   // 8192
#define PATCH_ELEMS (C * PS * PS) // 3072

// Per-frame running max of patch sums (float bits; all sums >= 0, so
// int-punned atomicMax preserves float ordering and zero-init is correct).
__device__ int          g_frame_max[T];   // zero-initialized
__device__ unsigned int g_count;          // zero-initialized

// ---------------------------------------------------------------------------
// Fused kernel: one CTA per patch computes sum |x - xr| over the patch,
// atomicMax into its frame slot, and the last CTA to finish performs the
// final mean-of-max + log, then resets global state for graph replay.
// ---------------------------------------------------------------------------
__global__ __launch_bounds__(256, 8)
void patch_loss_kernel(const float* __restrict__ x,
                       const float* __restrict__ xr,
                       float* __restrict__ out) {
    const int patch = blockIdx.x;          // [0, 8192)
    const int t   = patch >> 8;            // frame
    const int rem = patch & 255;
    const int ih  = rem >> 4;
    const int iw  = rem & 15;

    const int tid = threadIdx.x;           // [0, 256)
    const int r = tid >> 3;                // row within patch [0,32)
    const int q = tid & 7;                 // float4 index within row [0,8)

    const int hrow = ih * PS + r;
    const int wcol = iw * PS + q * 4;
    const int base0 = (t * H + hrow) * W + wcol;        // channel 0
    const int cstride = T * H * W;

    float s = 0.0f;
#pragma unroll
    for (int c = 0; c < C; ++c) {
        const int idx = base0 + c * cstride;
        const float4 a = __ldg(reinterpret_cast<const float4*>(x  + idx));
        const float4 b = __ldg(reinterpret_cast<const float4*>(xr + idx));
        s += fabsf(a.x - b.x) + fabsf(a.y - b.y)
           + fabsf(a.z - b.z) + fabsf(a.w - b.w);
    }

    // Block reduction: warp shfl then smem across 8 warps.
#pragma unroll
    for (int off = 16; off > 0; off >>= 1)
        s += __shfl_down_sync(0xFFFFFFFFu, s, off);

    __shared__ float warp_sums[8];
    __shared__ unsigned int s_isLast;
    const int lane = tid & 31;
    const int wid  = tid >> 5;
    if (lane == 0) warp_sums[wid] = s;
    __syncthreads();

    if (wid == 0) {
        float v = (lane < 8) ? warp_sums[lane] : 0.0f;
#pragma unroll
        for (int off = 4; off > 0; off >>= 1)
            v += __shfl_down_sync(0xFFFFFFFFu, v, off);

        unsigned int isLast = 0;
        if (lane == 0) {
            // v >= 0, so int compare == float compare
            atomicMax(&g_frame_max[t], __float_as_int(v));
            __threadfence();
            const unsigned int prev = atomicAdd(&g_count, 1u);
            isLast = (prev == (unsigned int)(NPATCH - 1)) ? 1u : 0u;
        }
        isLast = __shfl_sync(0xFFFFFFFFu, isLast, 0);

        if (isLast) {
            // All other CTAs' atomicMax writes are globally visible
            // (threadfence before their counter increment).
            const float fm = __int_as_float(__ldcg((const int*)&g_frame_max[lane]));
            float acc = fmaxf(fm, 0.0f);
#pragma unroll
            for (int off = 16; off > 0; off >>= 1)
                acc += __shfl_down_sync(0xFFFFFFFFu, acc, off);

            // Reset state for the next (graph-replayed) launch.
            g_frame_max[lane] = 0;
            if (lane == 0) {
                const float scale = 0.5f / ((float)PATCH_ELEMS * (float)T);
                out[0] = logf(acc * scale);
                __threadfence();
                g_count = 0u;
            }
        }
    }
}

extern "C" void kernel_launch(void* const* d_in, const int* in_sizes, int n_in,
                              void* d_out, int out_size) {
    const float* x  = (const float*)d_in[0];
    const float* xr = (const float*)d_in[1];
    float* out = (float*)d_out;

    patch_loss_kernel<<<NPATCH, 256>>>(x, xr, out);
}